// round 4
// baseline (speedup 1.0000x reference)
#include <cuda_runtime.h>
#include <math.h>

#define NN 50000
#define EE 800000
#define ET (EE + NN)
#define GG 64
#define F_IN 128
#define H1DIM 256   // HEADS * HID
#define H2DIM 32
#define NEG_SLOPE 0.2f

// ---------------- scratch ----------------
__device__ __align__(16) float g_h1[NN * H1DIM];
__device__ __align__(16) float g_out1[NN * H1DIM];
__device__ __align__(16) float g_as1[NN * 4];
__device__ __align__(16) float g_ad1[NN * 4];
__device__ __align__(16) float g_ex1[ET * 4];
__device__ __align__(16) float g_h2[NN * H2DIM];
__device__ float g_as2[NN];
__device__ float g_ad2[NN];
__device__ float g_ex2[ET];
__device__ float g_pool[GG * H2DIM];
__device__ float g_cnt[GG];
__device__ int g_deg[NN];          // zero at entry (zeroed by scatter each run)
__device__ int g_cur[NN];
__device__ int g_off[NN + 1];
__device__ int g_csr_src[ET];
__device__ int g_csr_dst[ET];
__device__ __align__(16) float g_wsd1[F_IN * 8];   // [f][s0..s3,d0..d3]
__device__ float g_wsd2[H1DIM * 2];                // [k][s,d]

// ---------------- helpers ----------------
__device__ __forceinline__ float leaky(float e) {
    return (e >= 0.f) ? e : NEG_SLOPE * e;
}
__device__ __forceinline__ unsigned long long pack2(float a, float b) {
    unsigned long long r;
    asm("mov.b64 %0, {%1, %2};" : "=l"(r) : "f"(a), "f"(b));
    return r;
}
__device__ __forceinline__ void unpack2(unsigned long long v, float& a, float& b) {
    asm("mov.b64 {%0, %1}, %2;" : "=f"(a), "=f"(b) : "l"(v));
}
__device__ __forceinline__ void fma2(unsigned long long& acc, unsigned long long a, unsigned long long b) {
    asm("fma.rn.f32x2 %0, %1, %2, %0;" : "+l"(acc) : "l"(a), "l"(b));
}

// ---------------- prep: folded attention vectors + zero pool ----------------
__global__ void prep_kernel(const float* __restrict__ W1,
                            const float* __restrict__ a1s, const float* __restrict__ a1d,
                            const float* __restrict__ W2,
                            const float* __restrict__ a2s, const float* __restrict__ a2d) {
    int tid = threadIdx.x;  // 1024
    {
        int f = tid >> 3, o = tid & 7;
        int h = o & 3, sd = o >> 2;
        const float* a = sd ? a1d : a1s;
        float s = 0.f;
#pragma unroll 8
        for (int d = 0; d < 64; d++) s += W1[f * H1DIM + h * 64 + d] * a[h * 64 + d];
        g_wsd1[f * 8 + o] = s;
    }
    if (tid < H1DIM * 2) {
        int k = tid >> 1, sd = tid & 1;
        const float* a = sd ? a2d : a2s;
        float s = 0.f;
#pragma unroll 8
        for (int d = 0; d < 32; d++) s += W2[k * H2DIM + d] * a[d];
        g_wsd2[k * 2 + sd] = s;
    }
    for (int j = tid; j < GG * H2DIM; j += 1024) g_pool[j] = 0.f;
    if (tid < GG) g_cnt[tid] = 0.f;
}

// ---------------- CSR build ----------------
__global__ void hist_kernel(const int* __restrict__ adj) {
    int e = blockIdx.x * blockDim.x + threadIdx.x;
    if (e >= ET) return;
    int dst = (e < EE) ? adj[EE + e] : e - EE;
    atomicAdd(&g_deg[dst], 1);
}

__global__ void scan_kernel() {
    __shared__ int part[1024];
    int tid = threadIdx.x;
    const int CH = (NN + 1023) / 1024;
    int start = tid * CH;
    int end = min(start + CH, NN);
    int s = 0;
    for (int i = start; i < end; i++) s += g_deg[i];
    part[tid] = s;
    __syncthreads();
    for (int off = 1; off < 1024; off <<= 1) {
        int v = (tid >= off) ? part[tid - off] : 0;
        __syncthreads();
        part[tid] += v;
        __syncthreads();
    }
    int base = (tid == 0) ? 0 : part[tid - 1];
    for (int i = start; i < end; i++) {
        g_off[i] = base;
        g_cur[i] = base;
        base += g_deg[i];
    }
    if (tid == 1023) g_off[NN] = part[1023];
}

__global__ void scatter_kernel(const int* __restrict__ adj) {
    int gt = blockIdx.x * blockDim.x + threadIdx.x;
    int stride = gridDim.x * blockDim.x;
    // deg already consumed by scan; zero it for the next replay
    for (int j = gt; j < NN; j += stride) g_deg[j] = 0;
    if (gt >= ET) return;
    int src, dst;
    if (gt < EE) { src = adj[gt]; dst = adj[EE + gt]; }
    else         { src = dst = gt - EE; }
    int p = atomicAdd(&g_cur[dst], 1);
    g_csr_src[p] = src;
    g_csr_dst[p] = dst;
}

// ---------------- GEMM1: h1 = x @ W1 (50000x128 @ 128x256), f32x2 ----------------
__global__ __launch_bounds__(256, 2) void gemm1_kernel(const float* __restrict__ x,
                                                       const float* __restrict__ W1) {
    __shared__ float xs[32][F_IN];  // 16kB
    int row0 = blockIdx.x * 32;
    int tid = threadIdx.x;
    const float4* xsrc = (const float4*)x;
    float4* xd = (float4*)&xs[0][0];
    int base = row0 * (F_IN / 4);
    const int LIM = NN * (F_IN / 4);
#pragma unroll
    for (int j = tid; j < 32 * F_IN / 4; j += 256) {
        int idx = base + j;
        xd[j] = (idx < LIM) ? xsrc[idx] : make_float4(0.f, 0.f, 0.f, 0.f);
    }
    __syncthreads();
    int col = tid;
    unsigned long long acc[32];
#pragma unroll
    for (int r = 0; r < 32; r++) acc[r] = 0ull;
#pragma unroll 1
    for (int k = 0; k < F_IN; k += 4) {
        float w0 = W1[k * H1DIM + col];
        float w1 = W1[(k + 1) * H1DIM + col];
        float w2 = W1[(k + 2) * H1DIM + col];
        float w3 = W1[(k + 3) * H1DIM + col];
        unsigned long long wp0 = pack2(w0, w1), wp1 = pack2(w2, w3);
#pragma unroll
        for (int r = 0; r < 32; r++) {
            float4 xv = *(const float4*)&xs[r][k];
            fma2(acc[r], pack2(xv.x, xv.y), wp0);
            fma2(acc[r], pack2(xv.z, xv.w), wp1);
        }
    }
#pragma unroll
    for (int r = 0; r < 32; r++) {
        int row = row0 + r;
        if (row < NN) {
            float lo, hi; unpack2(acc[r], lo, hi);
            g_h1[row * H1DIM + col] = lo + hi;
        }
    }
}

// ---------------- alpha1: as1/ad1 = x @ wsd1 (warp per node) ----------------
__global__ void alpha1_kernel(const float* __restrict__ x) {
    int gt = blockIdx.x * blockDim.x + threadIdx.x;
    int n = gt >> 5, lane = gt & 31;
    if (n >= NN) return;
    float4 xv = ((const float4*)x)[n * 32 + lane];
    float a0 = 0, a1 = 0, a2 = 0, a3 = 0, b0 = 0, b1 = 0, b2 = 0, b3 = 0;
    float xj[4] = {xv.x, xv.y, xv.z, xv.w};
#pragma unroll
    for (int j = 0; j < 4; j++) {
        int f = lane * 4 + j;
        float4 wa = *(const float4*)&g_wsd1[f * 8];
        float4 wb = *(const float4*)&g_wsd1[f * 8 + 4];
        a0 = fmaf(xj[j], wa.x, a0); a1 = fmaf(xj[j], wa.y, a1);
        a2 = fmaf(xj[j], wa.z, a2); a3 = fmaf(xj[j], wa.w, a3);
        b0 = fmaf(xj[j], wb.x, b0); b1 = fmaf(xj[j], wb.y, b1);
        b2 = fmaf(xj[j], wb.z, b2); b3 = fmaf(xj[j], wb.w, b3);
    }
#pragma unroll
    for (int off = 16; off; off >>= 1) {
        a0 += __shfl_xor_sync(0xffffffffu, a0, off);
        a1 += __shfl_xor_sync(0xffffffffu, a1, off);
        a2 += __shfl_xor_sync(0xffffffffu, a2, off);
        a3 += __shfl_xor_sync(0xffffffffu, a3, off);
        b0 += __shfl_xor_sync(0xffffffffu, b0, off);
        b1 += __shfl_xor_sync(0xffffffffu, b1, off);
        b2 += __shfl_xor_sync(0xffffffffu, b2, off);
        b3 += __shfl_xor_sync(0xffffffffu, b3, off);
    }
    if (lane == 0) {
        *(float4*)&g_as1[n * 4] = make_float4(a0, a1, a2, a3);
        *(float4*)&g_ad1[n * 4] = make_float4(b0, b1, b2, b3);
    }
}

// ---------------- edge exp (layer1), CSR order, no max, no atomics ----------------
__global__ void edge1_exp_kernel() {
    int p = blockIdx.x * blockDim.x + threadIdx.x;
    if (p >= ET) return;
    int src = g_csr_src[p], dst = g_csr_dst[p];
    float4 as = *(const float4*)&g_as1[src * 4];
    float4 ad = *(const float4*)&g_ad1[dst * 4];
    float4 ex;
    ex.x = expf(leaky(as.x + ad.x));
    ex.y = expf(leaky(as.y + ad.y));
    ex.z = expf(leaky(as.z + ad.z));
    ex.w = expf(leaky(as.w + ad.w));
    *(float4*)&g_ex1[p * 4] = ex;
}

// ---------------- agg1: out1 = relu((sum ex*h1[src]) / (sum ex) + b1) ----------------
__global__ void agg1_kernel(const float* __restrict__ b1) {
    int gt = blockIdx.x * blockDim.x + threadIdx.x;
    int n = gt >> 6;
    if (n >= NN) return;
    int c = gt & 63, head = c >> 4;
    int beg = g_off[n], end = g_off[n + 1];
    float4 acc = make_float4(0.f, 0.f, 0.f, 0.f);
    float den = 0.f;
    int i = beg;
    for (; i + 2 <= end; i += 2) {
        int s0 = g_csr_src[i], s1 = g_csr_src[i + 1];
        float e0 = g_ex1[i * 4 + head], e1 = g_ex1[(i + 1) * 4 + head];
        float4 v0 = *(const float4*)&g_h1[s0 * H1DIM + c * 4];
        float4 v1 = *(const float4*)&g_h1[s1 * H1DIM + c * 4];
        den += e0 + e1;
        acc.x = fmaf(e0, v0.x, fmaf(e1, v1.x, acc.x));
        acc.y = fmaf(e0, v0.y, fmaf(e1, v1.y, acc.y));
        acc.z = fmaf(e0, v0.z, fmaf(e1, v1.z, acc.z));
        acc.w = fmaf(e0, v0.w, fmaf(e1, v1.w, acc.w));
    }
    if (i < end) {
        int s0 = g_csr_src[i];
        float e0 = g_ex1[i * 4 + head];
        float4 v0 = *(const float4*)&g_h1[s0 * H1DIM + c * 4];
        den += e0;
        acc.x = fmaf(e0, v0.x, acc.x);
        acc.y = fmaf(e0, v0.y, acc.y);
        acc.z = fmaf(e0, v0.z, acc.z);
        acc.w = fmaf(e0, v0.w, acc.w);
    }
    float inv = 1.0f / den;
    float4 b = ((const float4*)b1)[c];
    float4 o;
    o.x = fmaxf(fmaf(acc.x, inv, b.x), 0.f);
    o.y = fmaxf(fmaf(acc.y, inv, b.y), 0.f);
    o.z = fmaxf(fmaf(acc.z, inv, b.z), 0.f);
    o.w = fmaxf(fmaf(acc.w, inv, b.w), 0.f);
    *(float4*)&g_out1[n * H1DIM + c * 4] = o;
}

// ---------------- GEMM2 + alpha2: h2 = out1 @ W2 (50000x256 @ 256x32) ----------------
__global__ __launch_bounds__(256, 2) void gemm2_kernel(const float* __restrict__ W2,
                                                       const float* __restrict__ a2s,
                                                       const float* __restrict__ a2d) {
    __shared__ float xs[16][H1DIM];          // 16kB
    __shared__ float ws[H1DIM * H2DIM];      // 32kB
    int row0 = blockIdx.x * 16;
    int tid = threadIdx.x;
    const float4* xsrc = (const float4*)g_out1;
    float4* xd = (float4*)&xs[0][0];
    int base = row0 * (H1DIM / 4);
    const int LIM = NN * (H1DIM / 4);
    for (int j = tid; j < 16 * H1DIM / 4; j += 256) {
        int idx = base + j;
        xd[j] = (idx < LIM) ? xsrc[idx] : make_float4(0.f, 0.f, 0.f, 0.f);
    }
    float4* wd = (float4*)ws;
    const float4* wsrc = (const float4*)W2;
    for (int j = tid; j < H1DIM * H2DIM / 4; j += 256) wd[j] = wsrc[j];
    __syncthreads();
    int c = tid & 31, rg = tid >> 5;
    int r0 = rg * 2;
    unsigned long long acc0 = 0ull, acc1 = 0ull;
#pragma unroll 1
    for (int k = 0; k < H1DIM; k += 4) {
        float w0 = ws[k * 32 + c], w1 = ws[(k + 1) * 32 + c];
        float w2 = ws[(k + 2) * 32 + c], w3 = ws[(k + 3) * 32 + c];
        unsigned long long wp0 = pack2(w0, w1), wp1 = pack2(w2, w3);
        float4 x0 = *(const float4*)&xs[r0][k];
        float4 x1 = *(const float4*)&xs[r0 + 1][k];
        fma2(acc0, pack2(x0.x, x0.y), wp0);
        fma2(acc0, pack2(x0.z, x0.w), wp1);
        fma2(acc1, pack2(x1.x, x1.y), wp0);
        fma2(acc1, pack2(x1.z, x1.w), wp1);
    }
    float l0, h0, l1, h1v;
    unpack2(acc0, l0, h0);
    unpack2(acc1, l1, h1v);
    float ha = l0 + h0, hb = l1 + h1v;
    int row_a = row0 + r0, row_b = row0 + r0 + 1;
    if (row_a < NN) g_h2[row_a * H2DIM + c] = ha;
    if (row_b < NN) g_h2[row_b * H2DIM + c] = hb;
    // fused alpha2
    float sa = a2s[c], da = a2d[c];
    float ps0 = ha * sa, pd0 = ha * da, ps1 = hb * sa, pd1 = hb * da;
#pragma unroll
    for (int off = 16; off; off >>= 1) {
        ps0 += __shfl_xor_sync(0xffffffffu, ps0, off);
        pd0 += __shfl_xor_sync(0xffffffffu, pd0, off);
        ps1 += __shfl_xor_sync(0xffffffffu, ps1, off);
        pd1 += __shfl_xor_sync(0xffffffffu, pd1, off);
    }
    if (c == 0) {
        if (row_a < NN) { g_as2[row_a] = ps0; g_ad2[row_a] = pd0; }
        if (row_b < NN) { g_as2[row_b] = ps1; g_ad2[row_b] = pd1; }
    }
}

// ---------------- edge exp (layer2) ----------------
__global__ void edge2_exp_kernel() {
    int p = blockIdx.x * blockDim.x + threadIdx.x;
    if (p >= ET) return;
    int src = g_csr_src[p], dst = g_csr_dst[p];
    g_ex2[p] = expf(leaky(g_as2[src] + g_ad2[dst]));
}

// ---------------- agg2 + bias + log_softmax + pool (warp per node) ----------------
__global__ void agg2_lsm_kernel(const float* __restrict__ b2, const int* __restrict__ batch) {
    int gt = blockIdx.x * blockDim.x + threadIdx.x;
    int n = gt >> 5;
    if (n >= NN) return;
    int lane = gt & 31;
    int beg = g_off[n], end = g_off[n + 1];
    float acc = 0.f, den = 0.f;
    int i = beg;
    for (; i + 2 <= end; i += 2) {
        int s0 = g_csr_src[i], s1 = g_csr_src[i + 1];
        float a0 = g_ex2[i], a1 = g_ex2[i + 1];
        float h0 = g_h2[s0 * H2DIM + lane], h1v = g_h2[s1 * H2DIM + lane];
        den += a0 + a1;
        acc = fmaf(a0, h0, fmaf(a1, h1v, acc));
    }
    if (i < end) {
        int s0 = g_csr_src[i];
        float a0 = g_ex2[i];
        den += a0;
        acc = fmaf(a0, g_h2[s0 * H2DIM + lane], acc);
    }
    float v = acc / den + b2[lane];
    float mx = v;
#pragma unroll
    for (int off = 16; off; off >>= 1) mx = fmaxf(mx, __shfl_xor_sync(0xffffffffu, mx, off));
    float ex = expf(v - mx);
    float s = ex;
#pragma unroll
    for (int off = 16; off; off >>= 1) s += __shfl_xor_sync(0xffffffffu, s, off);
    float lsm = v - mx - logf(s);
    int b = batch[n];
    atomicAdd(&g_pool[b * H2DIM + lane], lsm);
    if (lane == 0) atomicAdd(&g_cnt[b], 1.0f);
}

// ---------------- final ----------------
__global__ void final_kernel(const float* __restrict__ lin_W, const float* __restrict__ lin_b,
                             float* __restrict__ out) {
    int g = threadIdx.x;
    if (g >= GG) return;
    float inv = 1.0f / fmaxf(g_cnt[g], 1.0f);
    float acc = lin_b[0];
#pragma unroll
    for (int j = 0; j < H2DIM; j++) acc += g_pool[g * H2DIM + j] * inv * lin_W[j];
    out[g] = acc;
}

// ---------------- launcher ----------------
extern "C" void kernel_launch(void* const* d_in, const int* in_sizes, int n_in,
                              void* d_out, int out_size) {
    const float* x      = (const float*)d_in[0];
    const int*   adj    = (const int*)d_in[1];
    const int*   batch  = (const int*)d_in[2];
    const float* W1     = (const float*)d_in[3];
    const float* a1_src = (const float*)d_in[4];
    const float* a1_dst = (const float*)d_in[5];
    const float* b1     = (const float*)d_in[6];
    const float* W2     = (const float*)d_in[7];
    const float* a2_src = (const float*)d_in[8];
    const float* a2_dst = (const float*)d_in[9];
    const float* b2     = (const float*)d_in[10];
    const float* lin_W  = (const float*)d_in[11];
    const float* lin_b  = (const float*)d_in[12];
    float* out = (float*)d_out;

    const int TB = 256;
    int eb = (ET + TB - 1) / TB;

    prep_kernel<<<1, 1024>>>(W1, a1_src, a1_dst, W2, a2_src, a2_dst);
    hist_kernel<<<eb, TB>>>(adj);
    scan_kernel<<<1, 1024>>>();
    scatter_kernel<<<eb, TB>>>(adj);

    gemm1_kernel<<<(NN + 31) / 32, TB>>>(x, W1);
    alpha1_kernel<<<(NN * 32 + TB - 1) / TB, TB>>>(x);
    edge1_exp_kernel<<<eb, TB>>>();
    agg1_kernel<<<(NN * 64 + TB - 1) / TB, TB>>>(b1);

    gemm2_kernel<<<(NN + 15) / 16, TB>>>(W2, a2_src, a2_dst);
    edge2_exp_kernel<<<eb, TB>>>();
    agg2_lsm_kernel<<<(NN * 32 + TB - 1) / TB, TB>>>(b2, batch);

    final_kernel<<<1, 64>>>(lin_W, lin_b, out);
}